// round 13
// baseline (speedup 1.0000x reference)
#include <cuda_runtime.h>
#include <cuda_fp16.h>
#include <cstdint>

// Swin shifted-window attention, B=64, H=W=56, C=128, heads=4, hd=32, ws=7, shift=3.
// Round 12: fuse attn+proj into one kernel per (b,win); P stays in registers
// (QK accum fragment == PV A-fragment). qkv/wconv unchanged from R11.

#define BATCH 64
#define HW    56
#define CH    128
#define NWIN  64
#define SEQ   49
#define HEADS 4
#define HD    32
#define DISP  3
#define MPB   3136
#define MT64  49
#define PKH   72          // smem pitch (u32), 72 mod 32 = 8 -> conflict-free
#define QKV_SMEM ((64 + 2 * 128) * PKH * 4)   // 92160 B -> 2 CTA/SM

#define KT_P  24
#define PJ_P  40

// fused attn+proj smem layout (u32 offsets)
#define F_KT(h)  ((h) * (64 * KT_P))                  // 4 x 1536
#define F_VT(h)  (6144 + (h) * (32 * PJ_P))           // 4 x 1280
#define F_AS     11264                                 // 64 x PKH = 4608
#define F_BS     15872                                 // 128 x PKH = 9216
#define F_PS     25088                                 // 176 floats
#define FUSE_SMEM ((25088 + 176) * 4)                  // 101056 B

// fp16 scratch, pair-interleaved within 16-k groups (u32 = half2)
__device__ uint32_t g_q[(size_t)BATCH*HEADS*NWIN*SEQ*16];
__device__ uint32_t g_k[(size_t)BATCH*HEADS*NWIN*SEQ*16];
__device__ uint32_t g_v[(size_t)BATCH*HEADS*NWIN*SEQ*16];
__device__ uint32_t g_wqkv_h[384*64];
__device__ uint32_t g_wout_h[128*64];

__device__ __forceinline__ uint32_t f2h2(float a, float b) {
    __half2 h = __floats2half2_rn(a, b);
    return *(uint32_t*)&h;
}
__device__ __forceinline__ void mma16(float* c, const uint32_t* a, uint2 b) {
    asm volatile(
        "mma.sync.aligned.m16n8k16.row.col.f32.f16.f16.f32 "
        "{%0,%1,%2,%3}, {%4,%5,%6,%7}, {%8,%9}, {%0,%1,%2,%3};\n"
        : "+f"(c[0]), "+f"(c[1]), "+f"(c[2]), "+f"(c[3])
        : "r"(a[0]), "r"(a[1]), "r"(a[2]), "r"(a[3]), "r"(b.x), "r"(b.y));
}
__device__ __forceinline__ void stg16(uint32_t* dst, float4 f0, float4 f1, float4 f2, float4 f3) {
    *(uint4*)(dst)     = make_uint4(f2h2(f0.x,f0.y), f2h2(f2.x,f2.y), f2h2(f0.z,f0.w), f2h2(f2.z,f2.w));
    *(uint4*)(dst + 4) = make_uint4(f2h2(f1.x,f1.y), f2h2(f3.x,f3.y), f2h2(f1.z,f1.w), f2h2(f3.z,f3.w));
}
__device__ __forceinline__ uint32_t smem_u32(const void* p) {
    return (uint32_t)__cvta_generic_to_shared(p);
}
__device__ __forceinline__ void cp_async16(uint32_t dst, const void* src) {
    asm volatile("cp.async.cg.shared.global [%0], [%1], 16;" :: "r"(dst), "l"(src) : "memory");
}
__device__ __forceinline__ void cp_commit() {
    asm volatile("cp.async.commit_group;" ::: "memory");
}
template <int N>
__device__ __forceinline__ void cp_wait() {
    asm volatile("cp.async.wait_group %0;" :: "n"(N) : "memory");
}

// ---------------------------------------------------------------------------
// Kernel 0: one-time weight conversion into interleaved fp16.
// ---------------------------------------------------------------------------
__global__ __launch_bounds__(256) void wconv_kernel(const float* __restrict__ w_qkv,
                                                    const float* __restrict__ w_out) {
    const int idx = blockIdx.x * 256 + threadIdx.x;   // 4096 total
    const float* src;
    uint32_t* dst;
    int row, g;
    if (idx < 3072) { row = idx >> 3; g = idx & 7; src = w_qkv; dst = g_wqkv_h; }
    else            { int j = idx - 3072; row = j >> 3; g = j & 7; src = w_out; dst = g_wout_h; }
    const float4* sp = (const float4*)(src + (size_t)row * CH + g * 16);
    stg16(dst + row * 64 + g * 8, sp[0], sp[1], sp[2], sp[3]);
}

// ---------------------------------------------------------------------------
// Kernel 1: fused roll + QKV projection (unchanged from R11).
// ---------------------------------------------------------------------------
__global__ __launch_bounds__(256, 2) void qkv_mma_kernel(const float* __restrict__ x) {
    extern __shared__ uint32_t sh[];
    uint32_t* As = sh;
    uint32_t* Bs0 = sh + 64 * PKH;
    uint32_t* Bs1 = Bs0 + 128 * PKH;

    const int mtile = blockIdx.x, b = blockIdx.z;
    const int tid = threadIdx.x, lane = tid & 31, wid = tid >> 5;

    {
        #pragma unroll
        for (int it = 0; it < 8; ++it) {
            const int idx = tid + 256 * it;
            const int row = idx >> 4, c4 = idx & 15;
            cp_async16(smem_u32(Bs0 + row * PKH + c4 * 4),
                       g_wqkv_h + (size_t)row * 64 + c4 * 4);
        }
        cp_commit();
    }

    #pragma unroll
    for (int it = 0; it < 2; ++it) {
        const int idx = tid + 256 * it;
        const int row = idx >> 3, g = idx & 7;
        const int m = mtile * 64 + row;
        const int win = m / 49, s = m - win * 49;
        const int wr = win >> 3, wc = win & 7;
        const int i = s / 7, j = s - i * 7;
        int gh = wr * 7 + i + DISP; if (gh >= HW) gh -= HW;
        int gw = wc * 7 + j + DISP; if (gw >= HW) gw -= HW;
        const float4* sp = (const float4*)(x + (((size_t)b * HW + gh) * HW + gw) * CH + g * 16);
        stg16(As + row * PKH + g * 8, sp[0], sp[1], sp[2], sp[3]);
    }

    const int wm = wid & 1, wn = wid >> 1;
    const int m0 = wm * 32, n0 = wn * 32;
    const int c = lane & 3;

    #pragma unroll
    for (int chunk = 0; chunk < 3; ++chunk) {
        uint32_t* Bcur = (chunk & 1) ? Bs1 : Bs0;
        if (chunk < 2) {
            uint32_t* Bnext = (chunk & 1) ? Bs0 : Bs1;
            #pragma unroll
            for (int it = 0; it < 8; ++it) {
                const int idx = tid + 256 * it;
                const int row = idx >> 4, c4 = idx & 15;
                cp_async16(smem_u32(Bnext + row * PKH + c4 * 4),
                           g_wqkv_h + ((size_t)(chunk + 1) * 128 + row) * 64 + c4 * 4);
            }
            cp_commit();
            cp_wait<1>();
        } else {
            cp_wait<0>();
        }
        __syncthreads();

        float acc[2][4][4];
        #pragma unroll
        for (int mt = 0; mt < 2; ++mt)
            #pragma unroll
            for (int nt = 0; nt < 4; ++nt)
                #pragma unroll
                for (int q = 0; q < 4; ++q) acc[mt][nt][q] = 0.f;

        #pragma unroll
        for (int kk = 0; kk < 8; ++kk) {
            const int k0 = kk * 8 + 2 * c;
            const uint32_t* ar = As + (m0 + (lane >> 2)) * PKH + k0;
            const uint2 A10 = *(const uint2*)(ar);
            const uint2 A11 = *(const uint2*)(ar + 8 * PKH);
            const uint2 A20 = *(const uint2*)(ar + 16 * PKH);
            const uint2 A21 = *(const uint2*)(ar + 24 * PKH);
            const uint32_t a0[4] = {A10.x, A11.x, A10.y, A11.y};
            const uint32_t a1[4] = {A20.x, A21.x, A20.y, A21.y};
            #pragma unroll
            for (int nt = 0; nt < 4; ++nt) {
                const uint2 B = *(const uint2*)(Bcur + (n0 + nt * 8 + (lane >> 2)) * PKH + k0);
                mma16(acc[0][nt], a0, B);
                mma16(acc[1][nt], a1, B);
            }
        }

        uint32_t* gout = (chunk == 0) ? g_q : (chunk == 1) ? g_k : g_v;
        const float sc = (chunk == 0) ? 0.5f : 1.0f;
        #pragma unroll
        for (int mt = 0; mt < 2; ++mt) {
            #pragma unroll
            for (int hh = 0; hh < 2; ++hh) {
                const int m = mtile * 64 + m0 + mt * 16 + hh * 8 + (lane >> 2);
                const int win = m / 49, s = m - win * 49;
                const size_t rb = ((((size_t)b * HEADS + wn) * NWIN + win) * SEQ + s) * 16;
                #pragma unroll
                for (int nt = 0; nt < 4; ++nt) {
                    const int idx = 8 * (nt >> 1) + 2 * c + (nt & 1);
                    const float v0 = (hh == 0) ? acc[mt][nt][0] : acc[mt][nt][2];
                    const float v1 = (hh == 0) ? acc[mt][nt][1] : acc[mt][nt][3];
                    gout[rb + idx] = f2h2(sc * v0, sc * v1);
                }
            }
        }
        __syncthreads();
    }
}

// ---------------------------------------------------------------------------
// Kernel 2: fused attention + output projection. One block per (b, win).
// 512 threads = 16 warps. Warpgroup h (warps 4h..4h+3) does head h attention;
// output staged to As tile (fp16 interleaved); then all 16 warps do proj GEMM.
// w_out tile prefetched via cp.async, overlapping the attention phase.
// ---------------------------------------------------------------------------
__global__ __launch_bounds__(512, 1) void attn_proj_kernel(const float* __restrict__ pos,
                                                           const float* __restrict__ b_out,
                                                           float* __restrict__ out) {
    extern __shared__ uint32_t sh[];

    const int win = blockIdx.x, b = blockIdx.y;
    const int tid = threadIdx.x, lane = tid & 31, w = tid >> 5;
    const int head = w >> 2, wg = w & 3, htid = tid & 127;
    const size_t baseu = (((size_t)b * HEADS + head) * NWIN + win) * SEQ * 16;

    // prefetch w_out tile (overlaps attention)
    #pragma unroll
    for (int it = 0; it < 4; ++it) {
        const int idx = tid + 512 * it;
        const int row = idx >> 4, c4 = idx & 15;
        cp_async16(smem_u32(sh + F_BS + row * PKH + c4 * 4),
                   g_wout_h + (size_t)row * 64 + c4 * 4);
    }
    cp_commit();

    // K -> Kt[head] (rows >= SEQ zero); 128 threads per head.
    {
        uint32_t* Kt = sh + F_KT(head);
        const int r = htid >> 1, h = htid & 1;
        uint4* dst = (uint4*)(Kt + r * KT_P + h * 8);
        if (r < SEQ) {
            const uint4* sp = (const uint4*)(g_k + baseu + r * 16 + h * 8);
            dst[0] = sp[0]; dst[1] = sp[1];
        } else {
            dst[0] = make_uint4(0,0,0,0); dst[1] = make_uint4(0,0,0,0);
        }
    }
    // V -> VT[head] transposed
    {
        uint32_t* VT = sh + F_VT(head);
        #pragma unroll
        for (int it = 0; it < 8; ++it) {
            const int idx = htid + 128 * it;
            const int d = idx & 31, jp = idx >> 5;
            const int dp = d >> 1;
            const int vpos = (dp & 8) + 2 * (dp & 3) + ((dp >> 2) & 1);
            const int j0 = 2 * jp, j1 = 2 * jp + 1;
            uint32_t u0 = (j0 < SEQ) ? g_v[baseu + j0 * 16 + vpos] : 0u;
            uint32_t u1 = (j1 < SEQ) ? g_v[baseu + j1 * 16 + vpos] : 0u;
            const uint32_t h0 = (d & 1) ? (u0 >> 16) : (u0 & 0xFFFFu);
            const uint32_t h1 = (d & 1) ? (u1 >> 16) : (u1 & 0xFFFFu);
            const int ppos = (jp & 24) + 2 * (jp & 3) + ((jp >> 2) & 1);
            VT[d * PJ_P + ppos] = h0 | (h1 << 16);
        }
    }
    {
        float* ps = (float*)(sh + F_PS);
        if (tid < 169) ps[tid] = pos[tid];
    }
    __syncthreads();

    const float* ps = (const float*)(sh + F_PS);
    const int r1 = 16 * wg + (lane >> 2), r2 = r1 + 8;
    const int c = lane & 3;

    // Q fragments (pre-scaled by 0.5 in qkv)
    uint32_t a[2][4];
    #pragma unroll
    for (int kk = 0; kk < 2; ++kk) {
        uint2 q1 = make_uint2(0, 0), q2 = make_uint2(0, 0);
        if (r1 < SEQ) q1 = *(const uint2*)(g_q + baseu + r1 * 16 + kk * 8 + 2 * c);
        if (r2 < SEQ) q2 = *(const uint2*)(g_q + baseu + r2 * 16 + kk * 8 + 2 * c);
        a[kk][0] = q1.x; a[kk][1] = q2.x; a[kk][2] = q1.y; a[kk][3] = q2.y;
    }

    // scores 16x64 per warp
    float cc[8][4];
    #pragma unroll
    for (int nt = 0; nt < 8; ++nt)
        #pragma unroll
        for (int q = 0; q < 4; ++q) cc[nt][q] = 0.f;
    {
        const uint32_t* Kt = sh + F_KT(head);
        #pragma unroll
        for (int kk = 0; kk < 2; ++kk) {
            const int k0 = kk * 8 + 2 * c;
            #pragma unroll
            for (int nt = 0; nt < 8; ++nt) {
                const uint2 B = *(const uint2*)(Kt + (nt * 8 + (lane >> 2)) * KT_P + k0);
                mma16(cc[nt], a[kk], B);
            }
        }
    }

    // bias + shift mask
    const int wr = win >> 3, wc = win & 7;
    const bool mU = (wr == 7), mL = (wc == 7);
    const int ic1 = (r1 < SEQ) ? r1 : 48, ic2 = (r2 < SEQ) ? r2 : 48;
    const int xi1 = ic1 / 7, yi1 = ic1 - 7 * xi1;
    const int xi2 = ic2 / 7, yi2 = ic2 - 7 * xi2;
    #pragma unroll
    for (int nt = 0; nt < 8; ++nt) {
        #pragma unroll
        for (int e = 0; e < 2; ++e) {
            const int jj = nt * 8 + 2 * c + e;
            if (jj < SEQ) {
                const int xj = jj / 7, yj = jj - 7 * xj;
                cc[nt][e]     += ps[(xj - xi1 + 6) * 13 + (yj - yi1 + 6)];
                cc[nt][2 + e] += ps[(xj - xi2 + 6) * 13 + (yj - yi2 + 6)];
                if ((mU && ((xi1 >= 4) != (xj >= 4))) || (mL && ((yi1 >= 4) != (yj >= 4))))
                    cc[nt][e] = -1e30f;
                if ((mU && ((xi2 >= 4) != (xj >= 4))) || (mL && ((yi2 >= 4) != (yj >= 4))))
                    cc[nt][2 + e] = -1e30f;
            } else {
                cc[nt][e] = -1e30f;
                cc[nt][2 + e] = -1e30f;
            }
        }
    }

    // softmax across 4-lane row groups
    float mx1 = -1e30f, mx2 = -1e30f;
    #pragma unroll
    for (int nt = 0; nt < 8; ++nt) {
        mx1 = fmaxf(mx1, fmaxf(cc[nt][0], cc[nt][1]));
        mx2 = fmaxf(mx2, fmaxf(cc[nt][2], cc[nt][3]));
    }
    mx1 = fmaxf(mx1, __shfl_xor_sync(0xffffffffu, mx1, 1));
    mx1 = fmaxf(mx1, __shfl_xor_sync(0xffffffffu, mx1, 2));
    mx2 = fmaxf(mx2, __shfl_xor_sync(0xffffffffu, mx2, 1));
    mx2 = fmaxf(mx2, __shfl_xor_sync(0xffffffffu, mx2, 2));

    float sum1 = 0.f, sum2 = 0.f;
    #pragma unroll
    for (int nt = 0; nt < 8; ++nt) {
        cc[nt][0] = __expf(cc[nt][0] - mx1);
        cc[nt][1] = __expf(cc[nt][1] - mx1);
        cc[nt][2] = __expf(cc[nt][2] - mx2);
        cc[nt][3] = __expf(cc[nt][3] - mx2);
        sum1 += cc[nt][0] + cc[nt][1];
        sum2 += cc[nt][2] + cc[nt][3];
    }
    sum1 += __shfl_xor_sync(0xffffffffu, sum1, 1);
    sum1 += __shfl_xor_sync(0xffffffffu, sum1, 2);
    sum2 += __shfl_xor_sync(0xffffffffu, sum2, 1);
    sum2 += __shfl_xor_sync(0xffffffffu, sum2, 2);

    // PV with P straight from registers (accum fragment == A fragment)
    float o[4][4];
    #pragma unroll
    for (int nt = 0; nt < 4; ++nt)
        #pragma unroll
        for (int q = 0; q < 4; ++q) o[nt][q] = 0.f;
    {
        const uint32_t* VT = sh + F_VT(head);
        #pragma unroll
        for (int kk = 0; kk < 4; ++kk) {
            const int k0 = kk * 8 + 2 * c;
            const uint32_t ap[4] = { f2h2(cc[2*kk][0],   cc[2*kk][1]),
                                     f2h2(cc[2*kk][2],   cc[2*kk][3]),
                                     f2h2(cc[2*kk+1][0], cc[2*kk+1][1]),
                                     f2h2(cc[2*kk+1][2], cc[2*kk+1][3]) };
            #pragma unroll
            for (int nt = 0; nt < 4; ++nt) {
                const uint2 B = *(const uint2*)(VT + (nt * 8 + (lane >> 2)) * PJ_P + k0);
                mma16(o[nt], ap, B);
            }
        }
    }

    // stage normalized output into As tile (fp16 interleaved), rows 0..63
    {
        uint32_t* As = sh + F_AS;
        const float inv1 = 1.f / sum1, inv2 = 1.f / sum2;
        #pragma unroll
        for (int nt = 0; nt < 4; ++nt) {
            const int idx = head * 16 + 8 * (nt >> 1) + 2 * c + (nt & 1);
            As[r1 * PKH + idx] = f2h2(o[nt][0] * inv1, o[nt][1] * inv1);
            As[r2 * PKH + idx] = f2h2(o[nt][2] * inv2, o[nt][3] * inv2);
        }
    }
    cp_wait<0>();
    __syncthreads();

    // ---- proj GEMM: 16 warps, warp tile 16m x 32n ----
    const uint32_t* As = sh + F_AS;
    const uint32_t* Bs = sh + F_BS;
    const int wm = w & 3, wn = w >> 2;
    const int m0 = wm * 16, n0 = wn * 32;

    float acc[4][4];
    #pragma unroll
    for (int nt = 0; nt < 4; ++nt)
        #pragma unroll
        for (int q = 0; q < 4; ++q) acc[nt][q] = 0.f;

    #pragma unroll
    for (int kk = 0; kk < 8; ++kk) {
        const int k0 = kk * 8 + 2 * c;
        const uint32_t* ar = As + (m0 + (lane >> 2)) * PKH + k0;
        const uint2 A1 = *(const uint2*)(ar);
        const uint2 A2 = *(const uint2*)(ar + 8 * PKH);
        const uint32_t af[4] = {A1.x, A2.x, A1.y, A2.y};
        #pragma unroll
        for (int nt = 0; nt < 4; ++nt) {
            const uint2 B = *(const uint2*)(Bs + (n0 + nt * 8 + (lane >> 2)) * PKH + k0);
            mma16(acc[nt], af, B);
        }
    }

    // epilogue: bias + un-window + inverse roll scatter
    const int wrr = win >> 3, wcc = win & 7;
    #pragma unroll
    for (int hh = 0; hh < 2; ++hh) {
        const int s = m0 + hh * 8 + (lane >> 2);
        if (s < SEQ) {
            const int i = s / 7, j = s - i * 7;
            int gh = wrr * 7 + i + DISP; if (gh >= HW) gh -= HW;
            int gw = wcc * 7 + j + DISP; if (gw >= HW) gw -= HW;
            float* orow = out + (((size_t)b * HW + gh) * HW + gw) * CH;
            #pragma unroll
            for (int nt = 0; nt < 4; ++nt) {
                const int n = n0 + nt * 8 + 2 * c;
                float2 val = (hh == 0)
                    ? make_float2(acc[nt][0], acc[nt][1])
                    : make_float2(acc[nt][2], acc[nt][3]);
                val.x += __ldg(b_out + n);
                val.y += __ldg(b_out + n + 1);
                *(float2*)(orow + n) = val;
            }
        }
    }
}

extern "C" void kernel_launch(void* const* d_in, const int* in_sizes, int n_in,
                              void* d_out, int out_size) {
    const float* x      = (const float*)d_in[0];
    const float* w_qkv  = (const float*)d_in[1];
    const float* pos    = (const float*)d_in[2];
    const float* w_out  = (const float*)d_in[3];
    const float* b_out  = (const float*)d_in[4];
    float* out = (float*)d_out;

    cudaFuncSetAttribute(qkv_mma_kernel,  cudaFuncAttributeMaxDynamicSharedMemorySize, QKV_SMEM);
    cudaFuncSetAttribute(attn_proj_kernel, cudaFuncAttributeMaxDynamicSharedMemorySize, FUSE_SMEM);

    wconv_kernel<<<16, 256>>>(w_qkv, w_out);
    qkv_mma_kernel<<<dim3(MT64, 1, BATCH), 256, QKV_SMEM>>>(x);
    attn_proj_kernel<<<dim3(NWIN, BATCH), 512, FUSE_SMEM>>>(pos, b_out, out);
}

// round 15
// speedup vs baseline: 1.1783x; 1.1783x over previous
#include <cuda_runtime.h>
#include <cuda_fp16.h>
#include <cstdint>

// Swin shifted-window attention, B=64, H=W=56, C=128, heads=4, hd=32, ws=7, shift=3.
// Round 15 (= R14 resubmit + OOB-safe cp.async src clamp):
// attn: P-in-registers, cp.async K/V staging (zfill pads, clamped src),
// smem V-transpose, 6 CTAs/SM. qkv/proj/wconv unchanged from R11 (233.5us).

#define BATCH 64
#define HW    56
#define CH    128
#define NWIN  64
#define SEQ   49
#define HEADS 4
#define HD    32
#define DISP  3
#define MPB   3136
#define MT64  49
#define PKH   72          // smem pitch (u32), 72 mod 32 = 8 -> conflict-free
#define QKV_SMEM ((64 + 2 * 128) * PKH * 4)   // 92160 B -> 2 CTA/SM
#define PROJ_SMEM ((64 + 128) * PKH * 4)      // 55296 B

#define KT_P  24
#define PJ_P  40

// fp16 scratch, pair-interleaved within 16-k groups (u32 = half2)
__device__ uint32_t g_q[(size_t)BATCH*HEADS*NWIN*SEQ*16];
__device__ uint32_t g_k[(size_t)BATCH*HEADS*NWIN*SEQ*16];
__device__ uint32_t g_v[(size_t)BATCH*HEADS*NWIN*SEQ*16];
__device__ uint32_t g_attn[(size_t)BATCH*NWIN*SEQ*64];
__device__ uint32_t g_wqkv_h[384*64];
__device__ uint32_t g_wout_h[128*64];

__device__ __forceinline__ uint32_t f2h2(float a, float b) {
    __half2 h = __floats2half2_rn(a, b);
    return *(uint32_t*)&h;
}
__device__ __forceinline__ void mma16(float* c, const uint32_t* a, uint2 b) {
    asm volatile(
        "mma.sync.aligned.m16n8k16.row.col.f32.f16.f16.f32 "
        "{%0,%1,%2,%3}, {%4,%5,%6,%7}, {%8,%9}, {%0,%1,%2,%3};\n"
        : "+f"(c[0]), "+f"(c[1]), "+f"(c[2]), "+f"(c[3])
        : "r"(a[0]), "r"(a[1]), "r"(a[2]), "r"(a[3]), "r"(b.x), "r"(b.y));
}
__device__ __forceinline__ void stg16(uint32_t* dst, float4 f0, float4 f1, float4 f2, float4 f3) {
    *(uint4*)(dst)     = make_uint4(f2h2(f0.x,f0.y), f2h2(f2.x,f2.y), f2h2(f0.z,f0.w), f2h2(f2.z,f2.w));
    *(uint4*)(dst + 4) = make_uint4(f2h2(f1.x,f1.y), f2h2(f3.x,f3.y), f2h2(f1.z,f1.w), f2h2(f3.z,f3.w));
}
__device__ __forceinline__ uint32_t smem_u32(const void* p) {
    return (uint32_t)__cvta_generic_to_shared(p);
}
__device__ __forceinline__ void cp_async16(uint32_t dst, const void* src) {
    asm volatile("cp.async.cg.shared.global [%0], [%1], 16;" :: "r"(dst), "l"(src) : "memory");
}
// zero-fill variant: src-size 0 -> dst gets zeros. src must still be in-bounds
// (callers clamp), since an OOB generic address is risky even when ignored.
__device__ __forceinline__ void cp_async16z(uint32_t dst, const void* src, bool valid) {
    const int ss = valid ? 16 : 0;
    asm volatile("cp.async.cg.shared.global [%0], [%1], 16, %2;"
                 :: "r"(dst), "l"(src), "r"(ss) : "memory");
}
__device__ __forceinline__ void cp_commit() {
    asm volatile("cp.async.commit_group;" ::: "memory");
}
template <int N>
__device__ __forceinline__ void cp_wait() {
    asm volatile("cp.async.wait_group %0;" :: "n"(N) : "memory");
}

// ---------------------------------------------------------------------------
// Kernel 0: one-time weight conversion into interleaved fp16.
// ---------------------------------------------------------------------------
__global__ __launch_bounds__(256) void wconv_kernel(const float* __restrict__ w_qkv,
                                                    const float* __restrict__ w_out) {
    const int idx = blockIdx.x * 256 + threadIdx.x;   // 4096 total
    const float* src;
    uint32_t* dst;
    int row, g;
    if (idx < 3072) { row = idx >> 3; g = idx & 7; src = w_qkv; dst = g_wqkv_h; }
    else            { int j = idx - 3072; row = j >> 3; g = j & 7; src = w_out; dst = g_wout_h; }
    const float4* sp = (const float4*)(src + (size_t)row * CH + g * 16);
    stg16(dst + row * 64 + g * 8, sp[0], sp[1], sp[2], sp[3]);
}

// ---------------------------------------------------------------------------
// Kernel 1: fused roll + QKV projection (unchanged from R11).
// ---------------------------------------------------------------------------
__global__ __launch_bounds__(256, 2) void qkv_mma_kernel(const float* __restrict__ x) {
    extern __shared__ uint32_t sh[];
    uint32_t* As = sh;
    uint32_t* Bs0 = sh + 64 * PKH;
    uint32_t* Bs1 = Bs0 + 128 * PKH;

    const int mtile = blockIdx.x, b = blockIdx.z;
    const int tid = threadIdx.x, lane = tid & 31, wid = tid >> 5;

    {
        #pragma unroll
        for (int it = 0; it < 8; ++it) {
            const int idx = tid + 256 * it;
            const int row = idx >> 4, c4 = idx & 15;
            cp_async16(smem_u32(Bs0 + row * PKH + c4 * 4),
                       g_wqkv_h + (size_t)row * 64 + c4 * 4);
        }
        cp_commit();
    }

    #pragma unroll
    for (int it = 0; it < 2; ++it) {
        const int idx = tid + 256 * it;
        const int row = idx >> 3, g = idx & 7;
        const int m = mtile * 64 + row;
        const int win = m / 49, s = m - win * 49;
        const int wr = win >> 3, wc = win & 7;
        const int i = s / 7, j = s - i * 7;
        int gh = wr * 7 + i + DISP; if (gh >= HW) gh -= HW;
        int gw = wc * 7 + j + DISP; if (gw >= HW) gw -= HW;
        const float4* sp = (const float4*)(x + (((size_t)b * HW + gh) * HW + gw) * CH + g * 16);
        stg16(As + row * PKH + g * 8, sp[0], sp[1], sp[2], sp[3]);
    }

    const int wm = wid & 1, wn = wid >> 1;
    const int m0 = wm * 32, n0 = wn * 32;
    const int c = lane & 3;

    #pragma unroll
    for (int chunk = 0; chunk < 3; ++chunk) {
        uint32_t* Bcur = (chunk & 1) ? Bs1 : Bs0;
        if (chunk < 2) {
            uint32_t* Bnext = (chunk & 1) ? Bs0 : Bs1;
            #pragma unroll
            for (int it = 0; it < 8; ++it) {
                const int idx = tid + 256 * it;
                const int row = idx >> 4, c4 = idx & 15;
                cp_async16(smem_u32(Bnext + row * PKH + c4 * 4),
                           g_wqkv_h + ((size_t)(chunk + 1) * 128 + row) * 64 + c4 * 4);
            }
            cp_commit();
            cp_wait<1>();
        } else {
            cp_wait<0>();
        }
        __syncthreads();

        float acc[2][4][4];
        #pragma unroll
        for (int mt = 0; mt < 2; ++mt)
            #pragma unroll
            for (int nt = 0; nt < 4; ++nt)
                #pragma unroll
                for (int q = 0; q < 4; ++q) acc[mt][nt][q] = 0.f;

        #pragma unroll
        for (int kk = 0; kk < 8; ++kk) {
            const int k0 = kk * 8 + 2 * c;
            const uint32_t* ar = As + (m0 + (lane >> 2)) * PKH + k0;
            const uint2 A10 = *(const uint2*)(ar);
            const uint2 A11 = *(const uint2*)(ar + 8 * PKH);
            const uint2 A20 = *(const uint2*)(ar + 16 * PKH);
            const uint2 A21 = *(const uint2*)(ar + 24 * PKH);
            const uint32_t a0[4] = {A10.x, A11.x, A10.y, A11.y};
            const uint32_t a1[4] = {A20.x, A21.x, A20.y, A21.y};
            #pragma unroll
            for (int nt = 0; nt < 4; ++nt) {
                const uint2 B = *(const uint2*)(Bcur + (n0 + nt * 8 + (lane >> 2)) * PKH + k0);
                mma16(acc[0][nt], a0, B);
                mma16(acc[1][nt], a1, B);
            }
        }

        uint32_t* gout = (chunk == 0) ? g_q : (chunk == 1) ? g_k : g_v;
        const float sc = (chunk == 0) ? 0.5f : 1.0f;
        #pragma unroll
        for (int mt = 0; mt < 2; ++mt) {
            #pragma unroll
            for (int hh = 0; hh < 2; ++hh) {
                const int m = mtile * 64 + m0 + mt * 16 + hh * 8 + (lane >> 2);
                const int win = m / 49, s = m - win * 49;
                const size_t rb = ((((size_t)b * HEADS + wn) * NWIN + win) * SEQ + s) * 16;
                #pragma unroll
                for (int nt = 0; nt < 4; ++nt) {
                    const int idx = 8 * (nt >> 1) + 2 * c + (nt & 1);
                    const float v0 = (hh == 0) ? acc[mt][nt][0] : acc[mt][nt][2];
                    const float v1 = (hh == 0) ? acc[mt][nt][1] : acc[mt][nt][3];
                    gout[rb + idx] = f2h2(sc * v0, sc * v1);
                }
            }
        }
        __syncthreads();
    }
}

// ---------------------------------------------------------------------------
// Kernel 2: attention. One block per (b, win, head), 128 threads, 6 CTA/SM.
// cp.async K/V staging (clamped src for pad rows), smem V-transpose,
// P kept in registers.
// ---------------------------------------------------------------------------
__global__ __launch_bounds__(128, 6) void attn_mma_kernel(const float* __restrict__ pos) {
    __shared__ uint32_t Kt[64 * KT_P];    // [n][k16 interleaved], pad rows zero
    __shared__ uint32_t Vraw[64 * 16];    // raw g_v rows, pad rows zero
    __shared__ uint32_t VT[32 * PJ_P];    // [d][j pairs interleaved]
    __shared__ float    ps[176];

    const int blk  = blockIdx.x;
    const int head = blk & 3;
    const int win  = (blk >> 2) & 63;
    const int b    = blk >> 8;
    const int tid  = threadIdx.x, lane = tid & 31, w = tid >> 5;
    const size_t baseu = (((size_t)b * HEADS + head) * NWIN + win) * SEQ * 16;

    // async staging: K (64 rows x 16 u32) and Vraw, pad rows zero-filled.
    // src clamped to row 0 for invalid rows (address unused but kept in-bounds).
    #pragma unroll
    for (int it = 0; it < 2; ++it) {
        const int idx = tid + 128 * it;          // 256 chunks
        const int row = idx >> 2, c4 = idx & 3;
        const bool valid = row < SEQ;
        const int srow = valid ? row : 0;
        cp_async16z(smem_u32(Kt + row * KT_P + c4 * 4),
                    g_k + baseu + (size_t)srow * 16 + c4 * 4, valid);
    }
    #pragma unroll
    for (int it = 0; it < 2; ++it) {
        const int idx = tid + 128 * it;
        const int row = idx >> 2, c4 = idx & 3;
        const bool valid = row < SEQ;
        const int srow = valid ? row : 0;
        cp_async16z(smem_u32(Vraw + row * 16 + c4 * 4),
                    g_v + baseu + (size_t)srow * 16 + c4 * 4, valid);
    }
    cp_commit();

    // pos table (overlaps async copies)
    if (tid < 169) ps[tid] = pos[tid];
    if (tid + 128 < 169) ps[tid + 128] = pos[tid + 128];

    // Q fragments from gmem (pre-scaled by 0.5 in qkv) — overlaps copies too
    const int r1 = 16 * w + (lane >> 2), r2 = r1 + 8;
    const int c = lane & 3;
    uint32_t a[2][4];
    #pragma unroll
    for (int kk = 0; kk < 2; ++kk) {
        uint2 q1 = make_uint2(0, 0), q2 = make_uint2(0, 0);
        if (r1 < SEQ) q1 = *(const uint2*)(g_q + baseu + r1 * 16 + kk * 8 + 2 * c);
        if (r2 < SEQ) q2 = *(const uint2*)(g_q + baseu + r2 * 16 + kk * 8 + 2 * c);
        a[kk][0] = q1.x; a[kk][1] = q2.x; a[kk][2] = q1.y; a[kk][3] = q2.y;
    }

    cp_wait<0>();
    __syncthreads();

    // V transpose: smem -> smem (Vraw pad rows already zero)
    #pragma unroll
    for (int it = 0; it < 8; ++it) {
        const int idx = tid + 128 * it;
        const int d = idx & 31, jp = idx >> 5;
        const int dp = d >> 1;
        const int vpos = (dp & 8) + 2 * (dp & 3) + ((dp >> 2) & 1);
        const uint32_t u0 = Vraw[(2 * jp) * 16 + vpos];
        const uint32_t u1 = Vraw[(2 * jp + 1) * 16 + vpos];
        const uint32_t h0 = (d & 1) ? (u0 >> 16) : (u0 & 0xFFFFu);
        const uint32_t h1 = (d & 1) ? (u1 >> 16) : (u1 & 0xFFFFu);
        const int ppos = (jp & 24) + 2 * (jp & 3) + ((jp >> 2) & 1);
        VT[d * PJ_P + ppos] = h0 | (h1 << 16);
    }
    __syncthreads();

    // scores 16x64 per warp
    float cc[8][4];
    #pragma unroll
    for (int nt = 0; nt < 8; ++nt)
        #pragma unroll
        for (int q = 0; q < 4; ++q) cc[nt][q] = 0.f;
    #pragma unroll
    for (int kk = 0; kk < 2; ++kk) {
        const int k0 = kk * 8 + 2 * c;
        #pragma unroll
        for (int nt = 0; nt < 8; ++nt) {
            const uint2 B = *(const uint2*)(Kt + (nt * 8 + (lane >> 2)) * KT_P + k0);
            mma16(cc[nt], a[kk], B);
        }
    }

    // bias + shift mask
    const int wr = win >> 3, wc = win & 7;
    const bool mU = (wr == 7), mL = (wc == 7);
    const int ic1 = (r1 < SEQ) ? r1 : 48, ic2 = (r2 < SEQ) ? r2 : 48;
    const int xi1 = ic1 / 7, yi1 = ic1 - 7 * xi1;
    const int xi2 = ic2 / 7, yi2 = ic2 - 7 * xi2;
    #pragma unroll
    for (int nt = 0; nt < 8; ++nt) {
        #pragma unroll
        for (int e = 0; e < 2; ++e) {
            const int jj = nt * 8 + 2 * c + e;
            if (jj < SEQ) {
                const int xj = jj / 7, yj = jj - 7 * xj;
                cc[nt][e]     += ps[(xj - xi1 + 6) * 13 + (yj - yi1 + 6)];
                cc[nt][2 + e] += ps[(xj - xi2 + 6) * 13 + (yj - yi2 + 6)];
                if ((mU && ((xi1 >= 4) != (xj >= 4))) || (mL && ((yi1 >= 4) != (yj >= 4))))
                    cc[nt][e] = -1e30f;
                if ((mU && ((xi2 >= 4) != (xj >= 4))) || (mL && ((yi2 >= 4) != (yj >= 4))))
                    cc[nt][2 + e] = -1e30f;
            } else {
                cc[nt][e] = -1e30f;
                cc[nt][2 + e] = -1e30f;
            }
        }
    }

    // softmax across 4-lane row groups
    float mx1 = -1e30f, mx2 = -1e30f;
    #pragma unroll
    for (int nt = 0; nt < 8; ++nt) {
        mx1 = fmaxf(mx1, fmaxf(cc[nt][0], cc[nt][1]));
        mx2 = fmaxf(mx2, fmaxf(cc[nt][2], cc[nt][3]));
    }
    mx1 = fmaxf(mx1, __shfl_xor_sync(0xffffffffu, mx1, 1));
    mx1 = fmaxf(mx1, __shfl_xor_sync(0xffffffffu, mx1, 2));
    mx2 = fmaxf(mx2, __shfl_xor_sync(0xffffffffu, mx2, 1));
    mx2 = fmaxf(mx2, __shfl_xor_sync(0xffffffffu, mx2, 2));

    float sum1 = 0.f, sum2 = 0.f;
    #pragma unroll
    for (int nt = 0; nt < 8; ++nt) {
        cc[nt][0] = __expf(cc[nt][0] - mx1);
        cc[nt][1] = __expf(cc[nt][1] - mx1);
        cc[nt][2] = __expf(cc[nt][2] - mx2);
        cc[nt][3] = __expf(cc[nt][3] - mx2);
        sum1 += cc[nt][0] + cc[nt][1];
        sum2 += cc[nt][2] + cc[nt][3];
    }
    sum1 += __shfl_xor_sync(0xffffffffu, sum1, 1);
    sum1 += __shfl_xor_sync(0xffffffffu, sum1, 2);
    sum2 += __shfl_xor_sync(0xffffffffu, sum2, 1);
    sum2 += __shfl_xor_sync(0xffffffffu, sum2, 2);

    // PV with P straight from registers (QK accum fragment == PV A-fragment)
    float o[4][4];
    #pragma unroll
    for (int nt = 0; nt < 4; ++nt)
        #pragma unroll
        for (int q = 0; q < 4; ++q) o[nt][q] = 0.f;
    #pragma unroll
    for (int kk = 0; kk < 4; ++kk) {
        const int k0 = kk * 8 + 2 * c;
        const uint32_t ap[4] = { f2h2(cc[2*kk][0],   cc[2*kk][1]),
                                 f2h2(cc[2*kk][2],   cc[2*kk][3]),
                                 f2h2(cc[2*kk+1][0], cc[2*kk+1][1]),
                                 f2h2(cc[2*kk+1][2], cc[2*kk+1][3]) };
        #pragma unroll
        for (int nt = 0; nt < 4; ++nt) {
            const uint2 B = *(const uint2*)(VT + (nt * 8 + (lane >> 2)) * PJ_P + k0);
            mma16(o[nt], ap, B);
        }
    }

    const float inv1 = 1.f / sum1, inv2 = 1.f / sum2;
    #pragma unroll
    for (int nt = 0; nt < 4; ++nt) {
        const int idx = 8 * (nt >> 1) + 2 * c + (nt & 1);
        if (r1 < SEQ)
            g_attn[(((size_t)b * NWIN + win) * SEQ + r1) * 64 + head * 16 + idx] =
                f2h2(o[nt][0] * inv1, o[nt][1] * inv1);
        if (r2 < SEQ)
            g_attn[(((size_t)b * NWIN + win) * SEQ + r2) * 64 + head * 16 + idx] =
                f2h2(o[nt][2] * inv2, o[nt][3] * inv2);
    }
}

// ---------------------------------------------------------------------------
// Kernel 3: output projection via cp.async tiles + bias + inverse-roll scatter.
// ---------------------------------------------------------------------------
__global__ __launch_bounds__(256, 2) void proj_mma_kernel(const float* __restrict__ b_out,
                                                          float* __restrict__ out) {
    extern __shared__ uint32_t sh[];
    uint32_t* As = sh;
    uint32_t* Bs = sh + 64 * PKH;

    const int mtile = blockIdx.x, b = blockIdx.z;
    const int tid = threadIdx.x, lane = tid & 31, wid = tid >> 5;

    #pragma unroll
    for (int it = 0; it < 4; ++it) {
        const int idx = tid + 256 * it;
        const int row = idx >> 4, c4 = idx & 15;
        cp_async16(smem_u32(As + row * PKH + c4 * 4),
                   g_attn + ((size_t)b * MPB + mtile * 64 + row) * 64 + c4 * 4);
    }
    #pragma unroll
    for (int it = 0; it < 8; ++it) {
        const int idx = tid + 256 * it;
        const int row = idx >> 4, c4 = idx & 15;
        cp_async16(smem_u32(Bs + row * PKH + c4 * 4),
                   g_wout_h + (size_t)row * 64 + c4 * 4);
    }
    cp_commit();
    cp_wait<0>();
    __syncthreads();

    const int wm = wid & 1, wn = wid >> 1;
    const int m0 = wm * 32, n0 = wn * 32;

    float acc[2][4][4];
    #pragma unroll
    for (int mt = 0; mt < 2; ++mt)
        #pragma unroll
        for (int nt = 0; nt < 4; ++nt)
            #pragma unroll
            for (int q = 0; q < 4; ++q) acc[mt][nt][q] = 0.f;

    #pragma unroll
    for (int kk = 0; kk < 8; ++kk) {
        const int k0 = kk * 8 + 2 * (lane & 3);
        const uint32_t* ar = As + (m0 + (lane >> 2)) * PKH + k0;
        const uint2 A10 = *(const uint2*)(ar);
        const uint2 A11 = *(const uint2*)(ar + 8 * PKH);
        const uint2 A20 = *(const uint2*)(ar + 16 * PKH);
        const uint2 A21 = *(const uint2*)(ar + 24 * PKH);
        const uint32_t a0[4] = {A10.x, A11.x, A10.y, A11.y};
        const uint32_t a1[4] = {A20.x, A21.x, A20.y, A21.y};
        #pragma unroll
        for (int nt = 0; nt < 4; ++nt) {
            const uint2 B = *(const uint2*)(Bs + (n0 + nt * 8 + (lane >> 2)) * PKH + k0);
            mma16(acc[0][nt], a0, B);
            mma16(acc[1][nt], a1, B);
        }
    }

    #pragma unroll
    for (int mt = 0; mt < 2; ++mt) {
        #pragma unroll
        for (int hh = 0; hh < 2; ++hh) {
            const int m = mtile * 64 + m0 + mt * 16 + hh * 8 + (lane >> 2);
            const int win = m / 49, s = m - win * 49;
            const int wr = win >> 3, wc = win & 7;
            const int i = s / 7, j = s - i * 7;
            int gh = wr * 7 + i + DISP; if (gh >= HW) gh -= HW;
            int gw = wc * 7 + j + DISP; if (gw >= HW) gw -= HW;
            float* orow = out + (((size_t)b * HW + gh) * HW + gw) * CH;
            #pragma unroll
            for (int nt = 0; nt < 4; ++nt) {
                const int n = n0 + nt * 8 + 2 * (lane & 3);
                float2 val = (hh == 0)
                    ? make_float2(acc[mt][nt][0], acc[mt][nt][1])
                    : make_float2(acc[mt][nt][2], acc[mt][nt][3]);
                val.x += __ldg(b_out + n);
                val.y += __ldg(b_out + n + 1);
                *(float2*)(orow + n) = val;
            }
        }
    }
}

extern "C" void kernel_launch(void* const* d_in, const int* in_sizes, int n_in,
                              void* d_out, int out_size) {
    const float* x      = (const float*)d_in[0];
    const float* w_qkv  = (const float*)d_in[1];
    const float* pos    = (const float*)d_in[2];
    const float* w_out  = (const float*)d_in[3];
    const float* b_out  = (const float*)d_in[4];
    float* out = (float*)d_out;

    cudaFuncSetAttribute(qkv_mma_kernel,  cudaFuncAttributeMaxDynamicSharedMemorySize, QKV_SMEM);
    cudaFuncSetAttribute(proj_mma_kernel, cudaFuncAttributeMaxDynamicSharedMemorySize, PROJ_SMEM);

    wconv_kernel<<<16, 256>>>(w_qkv, w_out);
    qkv_mma_kernel<<<dim3(MT64, 1, BATCH), 256, QKV_SMEM>>>(x);
    attn_mma_kernel<<<BATCH * NWIN * HEADS, 128>>>(pos);
    proj_mma_kernel<<<dim3(MT64, 1, BATCH), 256, PROJ_SMEM>>>(b_out, out);
}

// round 16
// speedup vs baseline: 1.2684x; 1.0764x over previous
#include <cuda_runtime.h>
#include <cuda_fp16.h>
#include <cstdint>

// Swin shifted-window attention, B=64, H=W=56, C=128, heads=4, hd=32, ws=7, shift=3.
// Round 16: qkv occupancy push — single-buffer B (55KB smem), launch_bounds(256,3)
// -> 3 CTA/SM; uint2-paired epilogue stores. attn/proj/wconv unchanged from R15.

#define BATCH 64
#define HW    56
#define CH    128
#define NWIN  64
#define SEQ   49
#define HEADS 4
#define HD    32
#define DISP  3
#define MPB   3136
#define MT64  49
#define PKH   72          // smem pitch (u32), 72 mod 32 = 8 -> conflict-free
#define QKV_SMEM ((64 + 128) * PKH * 4)       // 55296 B -> 3 CTA/SM (with reg cap)
#define PROJ_SMEM ((64 + 128) * PKH * 4)      // 55296 B

#define KT_P  24
#define PJ_P  40

// fp16 scratch, pair-interleaved within 16-k groups (u32 = half2)
__device__ uint32_t g_q[(size_t)BATCH*HEADS*NWIN*SEQ*16];
__device__ uint32_t g_k[(size_t)BATCH*HEADS*NWIN*SEQ*16];
__device__ uint32_t g_v[(size_t)BATCH*HEADS*NWIN*SEQ*16];
__device__ uint32_t g_attn[(size_t)BATCH*NWIN*SEQ*64];
__device__ uint32_t g_wqkv_h[384*64];
__device__ uint32_t g_wout_h[128*64];

__device__ __forceinline__ uint32_t f2h2(float a, float b) {
    __half2 h = __floats2half2_rn(a, b);
    return *(uint32_t*)&h;
}
__device__ __forceinline__ void mma16(float* c, const uint32_t* a, uint2 b) {
    asm volatile(
        "mma.sync.aligned.m16n8k16.row.col.f32.f16.f16.f32 "
        "{%0,%1,%2,%3}, {%4,%5,%6,%7}, {%8,%9}, {%0,%1,%2,%3};\n"
        : "+f"(c[0]), "+f"(c[1]), "+f"(c[2]), "+f"(c[3])
        : "r"(a[0]), "r"(a[1]), "r"(a[2]), "r"(a[3]), "r"(b.x), "r"(b.y));
}
__device__ __forceinline__ void stg16(uint32_t* dst, float4 f0, float4 f1, float4 f2, float4 f3) {
    *(uint4*)(dst)     = make_uint4(f2h2(f0.x,f0.y), f2h2(f2.x,f2.y), f2h2(f0.z,f0.w), f2h2(f2.z,f2.w));
    *(uint4*)(dst + 4) = make_uint4(f2h2(f1.x,f1.y), f2h2(f3.x,f3.y), f2h2(f1.z,f1.w), f2h2(f3.z,f3.w));
}
__device__ __forceinline__ uint32_t smem_u32(const void* p) {
    return (uint32_t)__cvta_generic_to_shared(p);
}
__device__ __forceinline__ void cp_async16(uint32_t dst, const void* src) {
    asm volatile("cp.async.cg.shared.global [%0], [%1], 16;" :: "r"(dst), "l"(src) : "memory");
}
// zero-fill variant: src-size 0 -> dst gets zeros. callers clamp src in-bounds.
__device__ __forceinline__ void cp_async16z(uint32_t dst, const void* src, bool valid) {
    const int ss = valid ? 16 : 0;
    asm volatile("cp.async.cg.shared.global [%0], [%1], 16, %2;"
                 :: "r"(dst), "l"(src), "r"(ss) : "memory");
}
__device__ __forceinline__ void cp_commit() {
    asm volatile("cp.async.commit_group;" ::: "memory");
}
template <int N>
__device__ __forceinline__ void cp_wait() {
    asm volatile("cp.async.wait_group %0;" :: "n"(N) : "memory");
}

// ---------------------------------------------------------------------------
// Kernel 0: one-time weight conversion into interleaved fp16.
// ---------------------------------------------------------------------------
__global__ __launch_bounds__(256) void wconv_kernel(const float* __restrict__ w_qkv,
                                                    const float* __restrict__ w_out) {
    const int idx = blockIdx.x * 256 + threadIdx.x;   // 4096 total
    const float* src;
    uint32_t* dst;
    int row, g;
    if (idx < 3072) { row = idx >> 3; g = idx & 7; src = w_qkv; dst = g_wqkv_h; }
    else            { int j = idx - 3072; row = j >> 3; g = j & 7; src = w_out; dst = g_wout_h; }
    const float4* sp = (const float4*)(src + (size_t)row * CH + g * 16);
    stg16(dst + row * 64 + g * 8, sp[0], sp[1], sp[2], sp[3]);
}

// ---------------------------------------------------------------------------
// Kernel 1: fused roll + QKV projection. grid (49, 1, 64), block 256 = 8 warps,
// 3 CTA/SM. Single B buffer reloaded per chunk (weights are L2-hot).
// ---------------------------------------------------------------------------
__global__ __launch_bounds__(256, 3) void qkv_mma_kernel(const float* __restrict__ x) {
    extern __shared__ uint32_t sh[];
    uint32_t* As = sh;              // [64][PKH]
    uint32_t* Bs = sh + 64 * PKH;   // [128][PKH]

    const int mtile = blockIdx.x, b = blockIdx.z;
    const int tid = threadIdx.x, lane = tid & 31, wid = tid >> 5;

    // issue B chunk-0 load first (async), then overlap A gather with it.
    #pragma unroll
    for (int it = 0; it < 8; ++it) {
        const int idx = tid + 256 * it;
        const int row = idx >> 4, c4 = idx & 15;
        cp_async16(smem_u32(Bs + row * PKH + c4 * 4),
                   g_wqkv_h + (size_t)row * 64 + c4 * 4);
    }
    cp_commit();

    // A: 64 rows x 128k, rolled-window gather, fp32 -> fp16 interleaved (once).
    #pragma unroll
    for (int it = 0; it < 2; ++it) {
        const int idx = tid + 256 * it;
        const int row = idx >> 3, g = idx & 7;
        const int m = mtile * 64 + row;
        const int win = m / 49, s = m - win * 49;
        const int wr = win >> 3, wc = win & 7;
        const int i = s / 7, j = s - i * 7;
        int gh = wr * 7 + i + DISP; if (gh >= HW) gh -= HW;
        int gw = wc * 7 + j + DISP; if (gw >= HW) gw -= HW;
        const float4* sp = (const float4*)(x + (((size_t)b * HW + gh) * HW + gw) * CH + g * 16);
        stg16(As + row * PKH + g * 8, sp[0], sp[1], sp[2], sp[3]);
    }

    const int wm = wid & 1, wn = wid >> 1;
    const int m0 = wm * 32, n0 = wn * 32;
    const int c = lane & 3;

    for (int chunk = 0; chunk < 3; ++chunk) {
        if (chunk > 0) {
            __syncthreads();   // all warps done with previous Bs contents
            #pragma unroll
            for (int it = 0; it < 8; ++it) {
                const int idx = tid + 256 * it;
                const int row = idx >> 4, c4 = idx & 15;
                cp_async16(smem_u32(Bs + row * PKH + c4 * 4),
                           g_wqkv_h + ((size_t)chunk * 128 + row) * 64 + c4 * 4);
            }
            cp_commit();
        }
        cp_wait<0>();
        __syncthreads();

        float acc[2][4][4];
        #pragma unroll
        for (int mt = 0; mt < 2; ++mt)
            #pragma unroll
            for (int nt = 0; nt < 4; ++nt)
                #pragma unroll
                for (int q = 0; q < 4; ++q) acc[mt][nt][q] = 0.f;

        #pragma unroll
        for (int kk = 0; kk < 8; ++kk) {
            const int k0 = kk * 8 + 2 * c;
            const uint32_t* ar = As + (m0 + (lane >> 2)) * PKH + k0;
            const uint2 A10 = *(const uint2*)(ar);
            const uint2 A11 = *(const uint2*)(ar + 8 * PKH);
            const uint2 A20 = *(const uint2*)(ar + 16 * PKH);
            const uint2 A21 = *(const uint2*)(ar + 24 * PKH);
            const uint32_t a0[4] = {A10.x, A11.x, A10.y, A11.y};
            const uint32_t a1[4] = {A20.x, A21.x, A20.y, A21.y};
            #pragma unroll
            for (int nt = 0; nt < 4; ++nt) {
                const uint2 B = *(const uint2*)(Bs + (n0 + nt * 8 + (lane >> 2)) * PKH + k0);
                mma16(acc[0][nt], a0, B);
                mma16(acc[1][nt], a1, B);
            }
        }

        // epilogue: uint2-paired scatter (nt 0/1 adjacent, nt 2/3 adjacent)
        uint32_t* gout = (chunk == 0) ? g_q : (chunk == 1) ? g_k : g_v;
        const float sc = (chunk == 0) ? 0.5f : 1.0f;
        #pragma unroll
        for (int mt = 0; mt < 2; ++mt) {
            #pragma unroll
            for (int hh = 0; hh < 2; ++hh) {
                const int m = mtile * 64 + m0 + mt * 16 + hh * 8 + (lane >> 2);
                const int win = m / 49, s = m - win * 49;
                const size_t rb = ((((size_t)b * HEADS + wn) * NWIN + win) * SEQ + s) * 16;
                const int e0 = (hh == 0) ? 0 : 2, e1 = e0 + 1;
                const uint32_t p0 = f2h2(sc * acc[mt][0][e0], sc * acc[mt][0][e1]);
                const uint32_t p1 = f2h2(sc * acc[mt][1][e0], sc * acc[mt][1][e1]);
                const uint32_t p2 = f2h2(sc * acc[mt][2][e0], sc * acc[mt][2][e1]);
                const uint32_t p3 = f2h2(sc * acc[mt][3][e0], sc * acc[mt][3][e1]);
                *(uint2*)(gout + rb + 2 * c)     = make_uint2(p0, p1);
                *(uint2*)(gout + rb + 8 + 2 * c) = make_uint2(p2, p3);
            }
        }
    }
}

// ---------------------------------------------------------------------------
// Kernel 2: attention. One block per (b, win, head), 128 threads, 6 CTA/SM.
// cp.async K/V staging (clamped src), smem V-transpose, P in registers.
// ---------------------------------------------------------------------------
__global__ __launch_bounds__(128, 6) void attn_mma_kernel(const float* __restrict__ pos) {
    __shared__ uint32_t Kt[64 * KT_P];
    __shared__ uint32_t Vraw[64 * 16];
    __shared__ uint32_t VT[32 * PJ_P];
    __shared__ float    ps[176];

    const int blk  = blockIdx.x;
    const int head = blk & 3;
    const int win  = (blk >> 2) & 63;
    const int b    = blk >> 8;
    const int tid  = threadIdx.x, lane = tid & 31, w = tid >> 5;
    const size_t baseu = (((size_t)b * HEADS + head) * NWIN + win) * SEQ * 16;

    #pragma unroll
    for (int it = 0; it < 2; ++it) {
        const int idx = tid + 128 * it;
        const int row = idx >> 2, c4 = idx & 3;
        const bool valid = row < SEQ;
        const int srow = valid ? row : 0;
        cp_async16z(smem_u32(Kt + row * KT_P + c4 * 4),
                    g_k + baseu + (size_t)srow * 16 + c4 * 4, valid);
    }
    #pragma unroll
    for (int it = 0; it < 2; ++it) {
        const int idx = tid + 128 * it;
        const int row = idx >> 2, c4 = idx & 3;
        const bool valid = row < SEQ;
        const int srow = valid ? row : 0;
        cp_async16z(smem_u32(Vraw + row * 16 + c4 * 4),
                    g_v + baseu + (size_t)srow * 16 + c4 * 4, valid);
    }
    cp_commit();

    if (tid < 169) ps[tid] = pos[tid];
    if (tid + 128 < 169) ps[tid + 128] = pos[tid + 128];

    const int r1 = 16 * w + (lane >> 2), r2 = r1 + 8;
    const int c = lane & 3;
    uint32_t a[2][4];
    #pragma unroll
    for (int kk = 0; kk < 2; ++kk) {
        uint2 q1 = make_uint2(0, 0), q2 = make_uint2(0, 0);
        if (r1 < SEQ) q1 = *(const uint2*)(g_q + baseu + r1 * 16 + kk * 8 + 2 * c);
        if (r2 < SEQ) q2 = *(const uint2*)(g_q + baseu + r2 * 16 + kk * 8 + 2 * c);
        a[kk][0] = q1.x; a[kk][1] = q2.x; a[kk][2] = q1.y; a[kk][3] = q2.y;
    }

    cp_wait<0>();
    __syncthreads();

    #pragma unroll
    for (int it = 0; it < 8; ++it) {
        const int idx = tid + 128 * it;
        const int d = idx & 31, jp = idx >> 5;
        const int dp = d >> 1;
        const int vpos = (dp & 8) + 2 * (dp & 3) + ((dp >> 2) & 1);
        const uint32_t u0 = Vraw[(2 * jp) * 16 + vpos];
        const uint32_t u1 = Vraw[(2 * jp + 1) * 16 + vpos];
        const uint32_t h0 = (d & 1) ? (u0 >> 16) : (u0 & 0xFFFFu);
        const uint32_t h1 = (d & 1) ? (u1 >> 16) : (u1 & 0xFFFFu);
        const int ppos = (jp & 24) + 2 * (jp & 3) + ((jp >> 2) & 1);
        VT[d * PJ_P + ppos] = h0 | (h1 << 16);
    }
    __syncthreads();

    float cc[8][4];
    #pragma unroll
    for (int nt = 0; nt < 8; ++nt)
        #pragma unroll
        for (int q = 0; q < 4; ++q) cc[nt][q] = 0.f;
    #pragma unroll
    for (int kk = 0; kk < 2; ++kk) {
        const int k0 = kk * 8 + 2 * c;
        #pragma unroll
        for (int nt = 0; nt < 8; ++nt) {
            const uint2 B = *(const uint2*)(Kt + (nt * 8 + (lane >> 2)) * KT_P + k0);
            mma16(cc[nt], a[kk], B);
        }
    }

    const int wr = win >> 3, wc = win & 7;
    const bool mU = (wr == 7), mL = (wc == 7);
    const int ic1 = (r1 < SEQ) ? r1 : 48, ic2 = (r2 < SEQ) ? r2 : 48;
    const int xi1 = ic1 / 7, yi1 = ic1 - 7 * xi1;
    const int xi2 = ic2 / 7, yi2 = ic2 - 7 * xi2;
    #pragma unroll
    for (int nt = 0; nt < 8; ++nt) {
        #pragma unroll
        for (int e = 0; e < 2; ++e) {
            const int jj = nt * 8 + 2 * c + e;
            if (jj < SEQ) {
                const int xj = jj / 7, yj = jj - 7 * xj;
                cc[nt][e]     += ps[(xj - xi1 + 6) * 13 + (yj - yi1 + 6)];
                cc[nt][2 + e] += ps[(xj - xi2 + 6) * 13 + (yj - yi2 + 6)];
                if ((mU && ((xi1 >= 4) != (xj >= 4))) || (mL && ((yi1 >= 4) != (yj >= 4))))
                    cc[nt][e] = -1e30f;
                if ((mU && ((xi2 >= 4) != (xj >= 4))) || (mL && ((yi2 >= 4) != (yj >= 4))))
                    cc[nt][2 + e] = -1e30f;
            } else {
                cc[nt][e] = -1e30f;
                cc[nt][2 + e] = -1e30f;
            }
        }
    }

    float mx1 = -1e30f, mx2 = -1e30f;
    #pragma unroll
    for (int nt = 0; nt < 8; ++nt) {
        mx1 = fmaxf(mx1, fmaxf(cc[nt][0], cc[nt][1]));
        mx2 = fmaxf(mx2, fmaxf(cc[nt][2], cc[nt][3]));
    }
    mx1 = fmaxf(mx1, __shfl_xor_sync(0xffffffffu, mx1, 1));
    mx1 = fmaxf(mx1, __shfl_xor_sync(0xffffffffu, mx1, 2));
    mx2 = fmaxf(mx2, __shfl_xor_sync(0xffffffffu, mx2, 1));
    mx2 = fmaxf(mx2, __shfl_xor_sync(0xffffffffu, mx2, 2));

    float sum1 = 0.f, sum2 = 0.f;
    #pragma unroll
    for (int nt = 0; nt < 8; ++nt) {
        cc[nt][0] = __expf(cc[nt][0] - mx1);
        cc[nt][1] = __expf(cc[nt][1] - mx1);
        cc[nt][2] = __expf(cc[nt][2] - mx2);
        cc[nt][3] = __expf(cc[nt][3] - mx2);
        sum1 += cc[nt][0] + cc[nt][1];
        sum2 += cc[nt][2] + cc[nt][3];
    }
    sum1 += __shfl_xor_sync(0xffffffffu, sum1, 1);
    sum1 += __shfl_xor_sync(0xffffffffu, sum1, 2);
    sum2 += __shfl_xor_sync(0xffffffffu, sum2, 1);
    sum2 += __shfl_xor_sync(0xffffffffu, sum2, 2);

    float o[4][4];
    #pragma unroll
    for (int nt = 0; nt < 4; ++nt)
        #pragma unroll
        for (int q = 0; q < 4; ++q) o[nt][q] = 0.f;
    #pragma unroll
    for (int kk = 0; kk < 4; ++kk) {
        const int k0 = kk * 8 + 2 * c;
        const uint32_t ap[4] = { f2h2(cc[2*kk][0],   cc[2*kk][1]),
                                 f2h2(cc[2*kk][2],   cc[2*kk][3]),
                                 f2h2(cc[2*kk+1][0], cc[2*kk+1][1]),
                                 f2h2(cc[2*kk+1][2], cc[2*kk+1][3]) };
        #pragma unroll
        for (int nt = 0; nt < 4; ++nt) {
            const uint2 B = *(const uint2*)(VT + (nt * 8 + (lane >> 2)) * PJ_P + k0);
            mma16(o[nt], ap, B);
        }
    }

    // uint2-paired epilogue (nt 0/1 and 2/3 adjacent)
    const float inv1 = 1.f / sum1, inv2 = 1.f / sum2;
    {
        const size_t rbase = (((size_t)b * NWIN + win) * SEQ);
        if (r1 < SEQ) {
            uint32_t* o1 = g_attn + (rbase + r1) * 64 + head * 16;
            *(uint2*)(o1 + 2 * c)     = make_uint2(f2h2(o[0][0]*inv1, o[0][1]*inv1),
                                                   f2h2(o[1][0]*inv1, o[1][1]*inv1));
            *(uint2*)(o1 + 8 + 2 * c) = make_uint2(f2h2(o[2][0]*inv1, o[2][1]*inv1),
                                                   f2h2(o[3][0]*inv1, o[3][1]*inv1));
        }
        if (r2 < SEQ) {
            uint32_t* o2 = g_attn + (rbase + r2) * 64 + head * 16;
            *(uint2*)(o2 + 2 * c)     = make_uint2(f2h2(o[0][2]*inv2, o[0][3]*inv2),
                                                   f2h2(o[1][2]*inv2, o[1][3]*inv2));
            *(uint2*)(o2 + 8 + 2 * c) = make_uint2(f2h2(o[2][2]*inv2, o[2][3]*inv2),
                                                   f2h2(o[3][2]*inv2, o[3][3]*inv2));
        }
    }
}

// ---------------------------------------------------------------------------
// Kernel 3: output projection via cp.async tiles + bias + inverse-roll scatter.
// ---------------------------------------------------------------------------
__global__ __launch_bounds__(256, 2) void proj_mma_kernel(const float* __restrict__ b_out,
                                                          float* __restrict__ out) {
    extern __shared__ uint32_t sh[];
    uint32_t* As = sh;
    uint32_t* Bs = sh + 64 * PKH;

    const int mtile = blockIdx.x, b = blockIdx.z;
    const int tid = threadIdx.x, lane = tid & 31, wid = tid >> 5;

    #pragma unroll
    for (int it = 0; it < 4; ++it) {
        const int idx = tid + 256 * it;
        const int row = idx >> 4, c4 = idx & 15;
        cp_async16(smem_u32(As + row * PKH + c4 * 4),
                   g_attn + ((size_t)b * MPB + mtile * 64 + row) * 64 + c4 * 4);
    }
    #pragma unroll
    for (int it = 0; it < 8; ++it) {
        const int idx = tid + 256 * it;
        const int row = idx >> 4, c4 = idx & 15;
        cp_async16(smem_u32(Bs + row * PKH + c4 * 4),
                   g_wout_h + (size_t)row * 64 + c4 * 4);
    }
    cp_commit();
    cp_wait<0>();
    __syncthreads();

    const int wm = wid & 1, wn = wid >> 1;
    const int m0 = wm * 32, n0 = wn * 32;

    float acc[2][4][4];
    #pragma unroll
    for (int mt = 0; mt < 2; ++mt)
        #pragma unroll
        for (int nt = 0; nt < 4; ++nt)
            #pragma unroll
            for (int q = 0; q < 4; ++q) acc[mt][nt][q] = 0.f;

    #pragma unroll
    for (int kk = 0; kk < 8; ++kk) {
        const int k0 = kk * 8 + 2 * (lane & 3);
        const uint32_t* ar = As + (m0 + (lane >> 2)) * PKH + k0;
        const uint2 A10 = *(const uint2*)(ar);
        const uint2 A11 = *(const uint2*)(ar + 8 * PKH);
        const uint2 A20 = *(const uint2*)(ar + 16 * PKH);
        const uint2 A21 = *(const uint2*)(ar + 24 * PKH);
        const uint32_t a0[4] = {A10.x, A11.x, A10.y, A11.y};
        const uint32_t a1[4] = {A20.x, A21.x, A20.y, A21.y};
        #pragma unroll
        for (int nt = 0; nt < 4; ++nt) {
            const uint2 B = *(const uint2*)(Bs + (n0 + nt * 8 + (lane >> 2)) * PKH + k0);
            mma16(acc[0][nt], a0, B);
            mma16(acc[1][nt], a1, B);
        }
    }

    #pragma unroll
    for (int mt = 0; mt < 2; ++mt) {
        #pragma unroll
        for (int hh = 0; hh < 2; ++hh) {
            const int m = mtile * 64 + m0 + mt * 16 + hh * 8 + (lane >> 2);
            const int win = m / 49, s = m - win * 49;
            const int wr = win >> 3, wc = win & 7;
            const int i = s / 7, j = s - i * 7;
            int gh = wr * 7 + i + DISP; if (gh >= HW) gh -= HW;
            int gw = wc * 7 + j + DISP; if (gw >= HW) gw -= HW;
            float* orow = out + (((size_t)b * HW + gh) * HW + gw) * CH;
            #pragma unroll
            for (int nt = 0; nt < 4; ++nt) {
                const int n = n0 + nt * 8 + 2 * (lane & 3);
                float2 val = (hh == 0)
                    ? make_float2(acc[mt][nt][0], acc[mt][nt][1])
                    : make_float2(acc[mt][nt][2], acc[mt][nt][3]);
                val.x += __ldg(b_out + n);
                val.y += __ldg(b_out + n + 1);
                *(float2*)(orow + n) = val;
            }
        }
    }
}

extern "C" void kernel_launch(void* const* d_in, const int* in_sizes, int n_in,
                              void* d_out, int out_size) {
    const float* x      = (const float*)d_in[0];
    const float* w_qkv  = (const float*)d_in[1];
    const float* pos    = (const float*)d_in[2];
    const float* w_out  = (const float*)d_in[3];
    const float* b_out  = (const float*)d_in[4];
    float* out = (float*)d_out;

    cudaFuncSetAttribute(qkv_mma_kernel,  cudaFuncAttributeMaxDynamicSharedMemorySize, QKV_SMEM);
    cudaFuncSetAttribute(proj_mma_kernel, cudaFuncAttributeMaxDynamicSharedMemorySize, PROJ_SMEM);

    wconv_kernel<<<16, 256>>>(w_qkv, w_out);
    qkv_mma_kernel<<<dim3(MT64, 1, BATCH), 256, QKV_SMEM>>>(x);
    attn_mma_kernel<<<BATCH * NWIN * HEADS, 128>>>(pos);
    proj_mma_kernel<<<dim3(MT64, 1, BATCH), 256, PROJ_SMEM>>>(b_out, out);
}

// round 17
// speedup vs baseline: 1.2725x; 1.0032x over previous
#include <cuda_runtime.h>
#include <cuda_fp16.h>
#include <cstdint>

// Swin shifted-window attention, B=64, H=W=56, C=128, heads=4, hd=32, ws=7, shift=3.
// Round 17: occupancy push round 2 — qkv launch_bounds(256,4) (4 CTA/SM, 64-reg cap),
// proj launch_bounds(256,3). Everything else identical to R16 (218.2us).

#define BATCH 64
#define HW    56
#define CH    128
#define NWIN  64
#define SEQ   49
#define HEADS 4
#define HD    32
#define DISP  3
#define MPB   3136
#define MT64  49
#define PKH   72          // smem pitch (u32), 72 mod 32 = 8 -> conflict-free
#define QKV_SMEM ((64 + 128) * PKH * 4)       // 55296 B -> 4 CTA/SM w/ 64-reg cap
#define PROJ_SMEM ((64 + 128) * PKH * 4)      // 55296 B -> 3 CTA/SM

#define KT_P  24
#define PJ_P  40

// fp16 scratch, pair-interleaved within 16-k groups (u32 = half2)
__device__ uint32_t g_q[(size_t)BATCH*HEADS*NWIN*SEQ*16];
__device__ uint32_t g_k[(size_t)BATCH*HEADS*NWIN*SEQ*16];
__device__ uint32_t g_v[(size_t)BATCH*HEADS*NWIN*SEQ*16];
__device__ uint32_t g_attn[(size_t)BATCH*NWIN*SEQ*64];
__device__ uint32_t g_wqkv_h[384*64];
__device__ uint32_t g_wout_h[128*64];

__device__ __forceinline__ uint32_t f2h2(float a, float b) {
    __half2 h = __floats2half2_rn(a, b);
    return *(uint32_t*)&h;
}
__device__ __forceinline__ void mma16(float* c, const uint32_t* a, uint2 b) {
    asm volatile(
        "mma.sync.aligned.m16n8k16.row.col.f32.f16.f16.f32 "
        "{%0,%1,%2,%3}, {%4,%5,%6,%7}, {%8,%9}, {%0,%1,%2,%3};\n"
        : "+f"(c[0]), "+f"(c[1]), "+f"(c[2]), "+f"(c[3])
        : "r"(a[0]), "r"(a[1]), "r"(a[2]), "r"(a[3]), "r"(b.x), "r"(b.y));
}
__device__ __forceinline__ void stg16(uint32_t* dst, float4 f0, float4 f1, float4 f2, float4 f3) {
    *(uint4*)(dst)     = make_uint4(f2h2(f0.x,f0.y), f2h2(f2.x,f2.y), f2h2(f0.z,f0.w), f2h2(f2.z,f2.w));
    *(uint4*)(dst + 4) = make_uint4(f2h2(f1.x,f1.y), f2h2(f3.x,f3.y), f2h2(f1.z,f1.w), f2h2(f3.z,f3.w));
}
__device__ __forceinline__ uint32_t smem_u32(const void* p) {
    return (uint32_t)__cvta_generic_to_shared(p);
}
__device__ __forceinline__ void cp_async16(uint32_t dst, const void* src) {
    asm volatile("cp.async.cg.shared.global [%0], [%1], 16;" :: "r"(dst), "l"(src) : "memory");
}
// zero-fill variant: src-size 0 -> dst gets zeros. callers clamp src in-bounds.
__device__ __forceinline__ void cp_async16z(uint32_t dst, const void* src, bool valid) {
    const int ss = valid ? 16 : 0;
    asm volatile("cp.async.cg.shared.global [%0], [%1], 16, %2;"
                 :: "r"(dst), "l"(src), "r"(ss) : "memory");
}
__device__ __forceinline__ void cp_commit() {
    asm volatile("cp.async.commit_group;" ::: "memory");
}
template <int N>
__device__ __forceinline__ void cp_wait() {
    asm volatile("cp.async.wait_group %0;" :: "n"(N) : "memory");
}

// ---------------------------------------------------------------------------
// Kernel 0: one-time weight conversion into interleaved fp16.
// ---------------------------------------------------------------------------
__global__ __launch_bounds__(256) void wconv_kernel(const float* __restrict__ w_qkv,
                                                    const float* __restrict__ w_out) {
    const int idx = blockIdx.x * 256 + threadIdx.x;   // 4096 total
    const float* src;
    uint32_t* dst;
    int row, g;
    if (idx < 3072) { row = idx >> 3; g = idx & 7; src = w_qkv; dst = g_wqkv_h; }
    else            { int j = idx - 3072; row = j >> 3; g = j & 7; src = w_out; dst = g_wout_h; }
    const float4* sp = (const float4*)(src + (size_t)row * CH + g * 16);
    stg16(dst + row * 64 + g * 8, sp[0], sp[1], sp[2], sp[3]);
}

// ---------------------------------------------------------------------------
// Kernel 1: fused roll + QKV projection. grid (49, 1, 64), block 256 = 8 warps,
// 4 CTA/SM (64-reg cap). Single B buffer reloaded per chunk (L2-hot weights).
// ---------------------------------------------------------------------------
__global__ __launch_bounds__(256, 4) void qkv_mma_kernel(const float* __restrict__ x) {
    extern __shared__ uint32_t sh[];
    uint32_t* As = sh;              // [64][PKH]
    uint32_t* Bs = sh + 64 * PKH;   // [128][PKH]

    const int mtile = blockIdx.x, b = blockIdx.z;
    const int tid = threadIdx.x, lane = tid & 31, wid = tid >> 5;

    // issue B chunk-0 load first (async), then overlap A gather with it.
    #pragma unroll
    for (int it = 0; it < 8; ++it) {
        const int idx = tid + 256 * it;
        const int row = idx >> 4, c4 = idx & 15;
        cp_async16(smem_u32(Bs + row * PKH + c4 * 4),
                   g_wqkv_h + (size_t)row * 64 + c4 * 4);
    }
    cp_commit();

    // A: 64 rows x 128k, rolled-window gather, fp32 -> fp16 interleaved (once).
    #pragma unroll
    for (int it = 0; it < 2; ++it) {
        const int idx = tid + 256 * it;
        const int row = idx >> 3, g = idx & 7;
        const int m = mtile * 64 + row;
        const int win = m / 49, s = m - win * 49;
        const int wr = win >> 3, wc = win & 7;
        const int i = s / 7, j = s - i * 7;
        int gh = wr * 7 + i + DISP; if (gh >= HW) gh -= HW;
        int gw = wc * 7 + j + DISP; if (gw >= HW) gw -= HW;
        const float4* sp = (const float4*)(x + (((size_t)b * HW + gh) * HW + gw) * CH + g * 16);
        stg16(As + row * PKH + g * 8, sp[0], sp[1], sp[2], sp[3]);
    }

    const int wm = wid & 1, wn = wid >> 1;
    const int m0 = wm * 32, n0 = wn * 32;
    const int c = lane & 3;

    for (int chunk = 0; chunk < 3; ++chunk) {
        if (chunk > 0) {
            __syncthreads();   // all warps done with previous Bs contents
            #pragma unroll
            for (int it = 0; it < 8; ++it) {
                const int idx = tid + 256 * it;
                const int row = idx >> 4, c4 = idx & 15;
                cp_async16(smem_u32(Bs + row * PKH + c4 * 4),
                           g_wqkv_h + ((size_t)chunk * 128 + row) * 64 + c4 * 4);
            }
            cp_commit();
        }
        cp_wait<0>();
        __syncthreads();

        float acc[2][4][4];
        #pragma unroll
        for (int mt = 0; mt < 2; ++mt)
            #pragma unroll
            for (int nt = 0; nt < 4; ++nt)
                #pragma unroll
                for (int q = 0; q < 4; ++q) acc[mt][nt][q] = 0.f;

        #pragma unroll
        for (int kk = 0; kk < 8; ++kk) {
            const int k0 = kk * 8 + 2 * c;
            const uint32_t* ar = As + (m0 + (lane >> 2)) * PKH + k0;
            const uint2 A10 = *(const uint2*)(ar);
            const uint2 A11 = *(const uint2*)(ar + 8 * PKH);
            const uint2 A20 = *(const uint2*)(ar + 16 * PKH);
            const uint2 A21 = *(const uint2*)(ar + 24 * PKH);
            const uint32_t a0[4] = {A10.x, A11.x, A10.y, A11.y};
            const uint32_t a1[4] = {A20.x, A21.x, A20.y, A21.y};
            #pragma unroll
            for (int nt = 0; nt < 4; ++nt) {
                const uint2 B = *(const uint2*)(Bs + (n0 + nt * 8 + (lane >> 2)) * PKH + k0);
                mma16(acc[0][nt], a0, B);
                mma16(acc[1][nt], a1, B);
            }
        }

        // epilogue: uint2-paired scatter (nt 0/1 adjacent, nt 2/3 adjacent)
        uint32_t* gout = (chunk == 0) ? g_q : (chunk == 1) ? g_k : g_v;
        const float sc = (chunk == 0) ? 0.5f : 1.0f;
        #pragma unroll
        for (int mt = 0; mt < 2; ++mt) {
            #pragma unroll
            for (int hh = 0; hh < 2; ++hh) {
                const int m = mtile * 64 + m0 + mt * 16 + hh * 8 + (lane >> 2);
                const int win = m / 49, s = m - win * 49;
                const size_t rb = ((((size_t)b * HEADS + wn) * NWIN + win) * SEQ + s) * 16;
                const int e0 = (hh == 0) ? 0 : 2, e1 = e0 + 1;
                const uint32_t p0 = f2h2(sc * acc[mt][0][e0], sc * acc[mt][0][e1]);
                const uint32_t p1 = f2h2(sc * acc[mt][1][e0], sc * acc[mt][1][e1]);
                const uint32_t p2 = f2h2(sc * acc[mt][2][e0], sc * acc[mt][2][e1]);
                const uint32_t p3 = f2h2(sc * acc[mt][3][e0], sc * acc[mt][3][e1]);
                *(uint2*)(gout + rb + 2 * c)     = make_uint2(p0, p1);
                *(uint2*)(gout + rb + 8 + 2 * c) = make_uint2(p2, p3);
            }
        }
    }
}

// ---------------------------------------------------------------------------
// Kernel 2: attention. One block per (b, win, head), 128 threads, 6 CTA/SM.
// ---------------------------------------------------------------------------
__global__ __launch_bounds__(128, 6) void attn_mma_kernel(const float* __restrict__ pos) {
    __shared__ uint32_t Kt[64 * KT_P];
    __shared__ uint32_t Vraw[64 * 16];
    __shared__ uint32_t VT[32 * PJ_P];
    __shared__ float    ps[176];

    const int blk  = blockIdx.x;
    const int head = blk & 3;
    const int win  = (blk >> 2) & 63;
    const int b    = blk >> 8;
    const int tid  = threadIdx.x, lane = tid & 31, w = tid >> 5;
    const size_t baseu = (((size_t)b * HEADS + head) * NWIN + win) * SEQ * 16;

    #pragma unroll
    for (int it = 0; it < 2; ++it) {
        const int idx = tid + 128 * it;
        const int row = idx >> 2, c4 = idx & 3;
        const bool valid = row < SEQ;
        const int srow = valid ? row : 0;
        cp_async16z(smem_u32(Kt + row * KT_P + c4 * 4),
                    g_k + baseu + (size_t)srow * 16 + c4 * 4, valid);
    }
    #pragma unroll
    for (int it = 0; it < 2; ++it) {
        const int idx = tid + 128 * it;
        const int row = idx >> 2, c4 = idx & 3;
        const bool valid = row < SEQ;
        const int srow = valid ? row : 0;
        cp_async16z(smem_u32(Vraw + row * 16 + c4 * 4),
                    g_v + baseu + (size_t)srow * 16 + c4 * 4, valid);
    }
    cp_commit();

    if (tid < 169) ps[tid] = pos[tid];
    if (tid + 128 < 169) ps[tid + 128] = pos[tid + 128];

    const int r1 = 16 * w + (lane >> 2), r2 = r1 + 8;
    const int c = lane & 3;
    uint32_t a[2][4];
    #pragma unroll
    for (int kk = 0; kk < 2; ++kk) {
        uint2 q1 = make_uint2(0, 0), q2 = make_uint2(0, 0);
        if (r1 < SEQ) q1 = *(const uint2*)(g_q + baseu + r1 * 16 + kk * 8 + 2 * c);
        if (r2 < SEQ) q2 = *(const uint2*)(g_q + baseu + r2 * 16 + kk * 8 + 2 * c);
        a[kk][0] = q1.x; a[kk][1] = q2.x; a[kk][2] = q1.y; a[kk][3] = q2.y;
    }

    cp_wait<0>();
    __syncthreads();

    #pragma unroll
    for (int it = 0; it < 8; ++it) {
        const int idx = tid + 128 * it;
        const int d = idx & 31, jp = idx >> 5;
        const int dp = d >> 1;
        const int vpos = (dp & 8) + 2 * (dp & 3) + ((dp >> 2) & 1);
        const uint32_t u0 = Vraw[(2 * jp) * 16 + vpos];
        const uint32_t u1 = Vraw[(2 * jp + 1) * 16 + vpos];
        const uint32_t h0 = (d & 1) ? (u0 >> 16) : (u0 & 0xFFFFu);
        const uint32_t h1 = (d & 1) ? (u1 >> 16) : (u1 & 0xFFFFu);
        const int ppos = (jp & 24) + 2 * (jp & 3) + ((jp >> 2) & 1);
        VT[d * PJ_P + ppos] = h0 | (h1 << 16);
    }
    __syncthreads();

    float cc[8][4];
    #pragma unroll
    for (int nt = 0; nt < 8; ++nt)
        #pragma unroll
        for (int q = 0; q < 4; ++q) cc[nt][q] = 0.f;
    #pragma unroll
    for (int kk = 0; kk < 2; ++kk) {
        const int k0 = kk * 8 + 2 * c;
        #pragma unroll
        for (int nt = 0; nt < 8; ++nt) {
            const uint2 B = *(const uint2*)(Kt + (nt * 8 + (lane >> 2)) * KT_P + k0);
            mma16(cc[nt], a[kk], B);
        }
    }

    const int wr = win >> 3, wc = win & 7;
    const bool mU = (wr == 7), mL = (wc == 7);
    const int ic1 = (r1 < SEQ) ? r1 : 48, ic2 = (r2 < SEQ) ? r2 : 48;
    const int xi1 = ic1 / 7, yi1 = ic1 - 7 * xi1;
    const int xi2 = ic2 / 7, yi2 = ic2 - 7 * xi2;
    #pragma unroll
    for (int nt = 0; nt < 8; ++nt) {
        #pragma unroll
        for (int e = 0; e < 2; ++e) {
            const int jj = nt * 8 + 2 * c + e;
            if (jj < SEQ) {
                const int xj = jj / 7, yj = jj - 7 * xj;
                cc[nt][e]     += ps[(xj - xi1 + 6) * 13 + (yj - yi1 + 6)];
                cc[nt][2 + e] += ps[(xj - xi2 + 6) * 13 + (yj - yi2 + 6)];
                if ((mU && ((xi1 >= 4) != (xj >= 4))) || (mL && ((yi1 >= 4) != (yj >= 4))))
                    cc[nt][e] = -1e30f;
                if ((mU && ((xi2 >= 4) != (xj >= 4))) || (mL && ((yi2 >= 4) != (yj >= 4))))
                    cc[nt][2 + e] = -1e30f;
            } else {
                cc[nt][e] = -1e30f;
                cc[nt][2 + e] = -1e30f;
            }
        }
    }

    float mx1 = -1e30f, mx2 = -1e30f;
    #pragma unroll
    for (int nt = 0; nt < 8; ++nt) {
        mx1 = fmaxf(mx1, fmaxf(cc[nt][0], cc[nt][1]));
        mx2 = fmaxf(mx2, fmaxf(cc[nt][2], cc[nt][3]));
    }
    mx1 = fmaxf(mx1, __shfl_xor_sync(0xffffffffu, mx1, 1));
    mx1 = fmaxf(mx1, __shfl_xor_sync(0xffffffffu, mx1, 2));
    mx2 = fmaxf(mx2, __shfl_xor_sync(0xffffffffu, mx2, 1));
    mx2 = fmaxf(mx2, __shfl_xor_sync(0xffffffffu, mx2, 2));

    float sum1 = 0.f, sum2 = 0.f;
    #pragma unroll
    for (int nt = 0; nt < 8; ++nt) {
        cc[nt][0] = __expf(cc[nt][0] - mx1);
        cc[nt][1] = __expf(cc[nt][1] - mx1);
        cc[nt][2] = __expf(cc[nt][2] - mx2);
        cc[nt][3] = __expf(cc[nt][3] - mx2);
        sum1 += cc[nt][0] + cc[nt][1];
        sum2 += cc[nt][2] + cc[nt][3];
    }
    sum1 += __shfl_xor_sync(0xffffffffu, sum1, 1);
    sum1 += __shfl_xor_sync(0xffffffffu, sum1, 2);
    sum2 += __shfl_xor_sync(0xffffffffu, sum2, 1);
    sum2 += __shfl_xor_sync(0xffffffffu, sum2, 2);

    float o[4][4];
    #pragma unroll
    for (int nt = 0; nt < 4; ++nt)
        #pragma unroll
        for (int q = 0; q < 4; ++q) o[nt][q] = 0.f;
    #pragma unroll
    for (int kk = 0; kk < 4; ++kk) {
        const int k0 = kk * 8 + 2 * c;
        const uint32_t ap[4] = { f2h2(cc[2*kk][0],   cc[2*kk][1]),
                                 f2h2(cc[2*kk][2],   cc[2*kk][3]),
                                 f2h2(cc[2*kk+1][0], cc[2*kk+1][1]),
                                 f2h2(cc[2*kk+1][2], cc[2*kk+1][3]) };
        #pragma unroll
        for (int nt = 0; nt < 4; ++nt) {
            const uint2 B = *(const uint2*)(VT + (nt * 8 + (lane >> 2)) * PJ_P + k0);
            mma16(o[nt], ap, B);
        }
    }

    const float inv1 = 1.f / sum1, inv2 = 1.f / sum2;
    {
        const size_t rbase = (((size_t)b * NWIN + win) * SEQ);
        if (r1 < SEQ) {
            uint32_t* o1 = g_attn + (rbase + r1) * 64 + head * 16;
            *(uint2*)(o1 + 2 * c)     = make_uint2(f2h2(o[0][0]*inv1, o[0][1]*inv1),
                                                   f2h2(o[1][0]*inv1, o[1][1]*inv1));
            *(uint2*)(o1 + 8 + 2 * c) = make_uint2(f2h2(o[2][0]*inv1, o[2][1]*inv1),
                                                   f2h2(o[3][0]*inv1, o[3][1]*inv1));
        }
        if (r2 < SEQ) {
            uint32_t* o2 = g_attn + (rbase + r2) * 64 + head * 16;
            *(uint2*)(o2 + 2 * c)     = make_uint2(f2h2(o[0][2]*inv2, o[0][3]*inv2),
                                                   f2h2(o[1][2]*inv2, o[1][3]*inv2));
            *(uint2*)(o2 + 8 + 2 * c) = make_uint2(f2h2(o[2][2]*inv2, o[2][3]*inv2),
                                                   f2h2(o[3][2]*inv2, o[3][3]*inv2));
        }
    }
}

// ---------------------------------------------------------------------------
// Kernel 3: output projection via cp.async tiles + bias + inverse-roll scatter.
// 3 CTA/SM.
// ---------------------------------------------------------------------------
__global__ __launch_bounds__(256, 3) void proj_mma_kernel(const float* __restrict__ b_out,
                                                          float* __restrict__ out) {
    extern __shared__ uint32_t sh[];
    uint32_t* As = sh;
    uint32_t* Bs = sh + 64 * PKH;

    const int mtile = blockIdx.x, b = blockIdx.z;
    const int tid = threadIdx.x, lane = tid & 31, wid = tid >> 5;

    #pragma unroll
    for (int it = 0; it < 4; ++it) {
        const int idx = tid + 256 * it;
        const int row = idx >> 4, c4 = idx & 15;
        cp_async16(smem_u32(As + row * PKH + c4 * 4),
                   g_attn + ((size_t)b * MPB + mtile * 64 + row) * 64 + c4 * 4);
    }
    #pragma unroll
    for (int it = 0; it < 8; ++it) {
        const int idx = tid + 256 * it;
        const int row = idx >> 4, c4 = idx & 15;
        cp_async16(smem_u32(Bs + row * PKH + c4 * 4),
                   g_wout_h + (size_t)row * 64 + c4 * 4);
    }
    cp_commit();
    cp_wait<0>();
    __syncthreads();

    const int wm = wid & 1, wn = wid >> 1;
    const int m0 = wm * 32, n0 = wn * 32;

    float acc[2][4][4];
    #pragma unroll
    for (int mt = 0; mt < 2; ++mt)
        #pragma unroll
        for (int nt = 0; nt < 4; ++nt)
            #pragma unroll
            for (int q = 0; q < 4; ++q) acc[mt][nt][q] = 0.f;

    #pragma unroll
    for (int kk = 0; kk < 8; ++kk) {
        const int k0 = kk * 8 + 2 * (lane & 3);
        const uint32_t* ar = As + (m0 + (lane >> 2)) * PKH + k0;
        const uint2 A10 = *(const uint2*)(ar);
        const uint2 A11 = *(const uint2*)(ar + 8 * PKH);
        const uint2 A20 = *(const uint2*)(ar + 16 * PKH);
        const uint2 A21 = *(const uint2*)(ar + 24 * PKH);
        const uint32_t a0[4] = {A10.x, A11.x, A10.y, A11.y};
        const uint32_t a1[4] = {A20.x, A21.x, A20.y, A21.y};
        #pragma unroll
        for (int nt = 0; nt < 4; ++nt) {
            const uint2 B = *(const uint2*)(Bs + (n0 + nt * 8 + (lane >> 2)) * PKH + k0);
            mma16(acc[0][nt], a0, B);
            mma16(acc[1][nt], a1, B);
        }
    }

    #pragma unroll
    for (int mt = 0; mt < 2; ++mt) {
        #pragma unroll
        for (int hh = 0; hh < 2; ++hh) {
            const int m = mtile * 64 + m0 + mt * 16 + hh * 8 + (lane >> 2);
            const int win = m / 49, s = m - win * 49;
            const int wr = win >> 3, wc = win & 7;
            const int i = s / 7, j = s - i * 7;
            int gh = wr * 7 + i + DISP; if (gh >= HW) gh -= HW;
            int gw = wc * 7 + j + DISP; if (gw >= HW) gw -= HW;
            float* orow = out + (((size_t)b * HW + gh) * HW + gw) * CH;
            #pragma unroll
            for (int nt = 0; nt < 4; ++nt) {
                const int n = n0 + nt * 8 + 2 * (lane & 3);
                float2 val = (hh == 0)
                    ? make_float2(acc[mt][nt][0], acc[mt][nt][1])
                    : make_float2(acc[mt][nt][2], acc[mt][nt][3]);
                val.x += __ldg(b_out + n);
                val.y += __ldg(b_out + n + 1);
                *(float2*)(orow + n) = val;
            }
        }
    }
}

extern "C" void kernel_launch(void* const* d_in, const int* in_sizes, int n_in,
                              void* d_out, int out_size) {
    const float* x      = (const float*)d_in[0];
    const float* w_qkv  = (const float*)d_in[1];
    const float* pos    = (const float*)d_in[2];
    const float* w_out  = (const float*)d_in[3];
    const float* b_out  = (const float*)d_in[4];
    float* out = (float*)d_out;

    cudaFuncSetAttribute(qkv_mma_kernel,  cudaFuncAttributeMaxDynamicSharedMemorySize, QKV_SMEM);
    cudaFuncSetAttribute(proj_mma_kernel, cudaFuncAttributeMaxDynamicSharedMemorySize, PROJ_SMEM);

    wconv_kernel<<<16, 256>>>(w_qkv, w_out);
    qkv_mma_kernel<<<dim3(MT64, 1, BATCH), 256, QKV_SMEM>>>(x);
    attn_mma_kernel<<<BATCH * NWIN * HEADS, 128>>>(pos);
    proj_mma_kernel<<<dim3(MT64, 1, BATCH), 256, PROJ_SMEM>>>(b_out, out);
}